// round 13
// baseline (speedup 1.0000x reference)
#include <cuda_runtime.h>
#include <cuda_bf16.h>
#include <cstdint>
#include <float.h>

// Problem constants
#define N_ROWS 16384   // 16*32*32
#define DIM    256
#define NEMB   2048
#define KTOP   4
#define KCAND  16      // approx candidates per row (exact-rescored)

#define BM 128
#define BN 128
#define KC 32          // k-chunk in the mma kernel
#define APAD 40        // padded smem row (bf16) -> conflict-free frags, 16B aligned
#define OUTBLOCKS 512

// Scratch (no cudaMalloc allowed)
__device__ float g_codeT[NEMB * DIM];                 // codebook [code][dim] fp32
__device__ __align__(16) __nv_bfloat16 g_ebf[NEMB * DIM];   // bf16 codebook [code][dim]
__device__ __align__(16) __nv_bfloat16 g_xbf[N_ROWS * DIM]; // bf16 input rows
__device__ float g_enorm[NEMB];          // ||e||^2 (R11 exact emitter: fma partials + tree32)
__device__ float g_xnorm[N_ROWS];        // ||x||^2 (R11 form)
__device__ int   g_cand[N_ROWS * KCAND]; // approx top-16 indices
__device__ int   g_top[N_ROWS * KTOP];   // exact top-4 (hi-index tie policy)
__device__ float g_key2[N_ROWS * 2];     // exact top-2 keys (argmax low-index policy)
__device__ double g_partial[OUTBLOCKS];

// ---------------------------------------------------------------------------
// Kernel 1: transpose embed [DIM][NEMB] -> codeT [NEMB][DIM] (+ bf16 copy)
// ---------------------------------------------------------------------------
__global__ void k_transpose(const float* __restrict__ embed) {
    __shared__ float t[32][33];
    int c = blockIdx.x * 32 + threadIdx.x;
#pragma unroll
    for (int j = 0; j < 4; j++) {
        int d = blockIdx.y * 32 + threadIdx.y + j * 8;
        t[threadIdx.y + j * 8][threadIdx.x] = embed[d * NEMB + c];
    }
    __syncthreads();
    int d = blockIdx.y * 32 + threadIdx.x;
#pragma unroll
    for (int j = 0; j < 4; j++) {
        int c2 = blockIdx.x * 32 + threadIdx.y + j * 8;
        float v = t[threadIdx.x][threadIdx.y + j * 8];
        g_codeT[c2 * DIM + d] = v;
        g_ebf[c2 * DIM + d]   = __float2bfloat16(v);
    }
}

// ---------------------------------------------------------------------------
// Kernel 2: ||e_c||^2 — EXACT R11 emitter (fma partials stride-32, tree32)
// ---------------------------------------------------------------------------
__global__ void k_enorm(const float* __restrict__ embed) {
    __shared__ float p[32][33];
    int c  = blockIdx.x * 32 + threadIdx.x;
    int ty = threadIdx.y;
    float s = 0.f;
#pragma unroll
    for (int i = 0; i < DIM / 32; i++) {
        float v = embed[(size_t)(ty + 32 * i) * NEMB + c];
        s = __fmaf_rn(v, v, s);
    }
    p[ty][threadIdx.x] = s;
    __syncthreads();
#pragma unroll
    for (int step = 16; step > 0; step >>= 1) {
        if (ty < step) p[ty][threadIdx.x] = __fadd_rn(p[ty][threadIdx.x], p[ty + step][threadIdx.x]);
        __syncthreads();
    }
    if (ty == 0) g_enorm[c] = p[0][threadIdx.x];
}

// ---------------------------------------------------------------------------
// Kernel 3: ||x_r||^2 (R11 form, flip-inert)
// ---------------------------------------------------------------------------
__global__ void k_xnorm(const float* __restrict__ input) {
    int row  = blockIdx.x * 8 + (threadIdx.x >> 5);
    int lane = threadIdx.x & 31;
    float s = 0.f;
#pragma unroll
    for (int i = 0; i < DIM / 32; i++) {
        float v = input[(size_t)row * DIM + lane + 32 * i];
        s = __fmaf_rn(v, v, s);
    }
#pragma unroll
    for (int o = 16; o; o >>= 1)
        s = __fadd_rn(s, __shfl_down_sync(0xffffffffu, s, o));
    if (lane == 0) g_xnorm[row] = s;
}

// ---------------------------------------------------------------------------
// Kernel 4: input -> bf16
// ---------------------------------------------------------------------------
__global__ void k_xbf(const float* __restrict__ input) {
    int gsz = gridDim.x * blockDim.x;
    for (int i = blockIdx.x * blockDim.x + threadIdx.x; i < N_ROWS * DIM / 2; i += gsz) {
        float2 v = ((const float2*)input)[i];
        __nv_bfloat162 h;
        h.x = __float2bfloat16(v.x);
        h.y = __float2bfloat16(v.y);
        ((__nv_bfloat162*)g_xbf)[i] = h;
    }
}

// Tie order (XLA TopK bitonic): smaller key wins; exact tie -> HIGHER index.
__device__ __forceinline__ bool kbetter(float k1, int i1, float k2, int i2) {
    return (k1 < k2) || (k1 == k2 && i1 > i2);
}

__device__ __forceinline__ void try_insert(volatile float* rk, volatile int* ri,
                                           int* lock, float kv, int c) {
    if (kbetter(kv, c, rk[KCAND - 1], ri[KCAND - 1])) {
        while (atomicCAS(lock, 0, 1) != 0) {}
        __threadfence_block();
        if (kbetter(kv, c, rk[KCAND - 1], ri[KCAND - 1])) {
            int p = KCAND - 1;
            while (p > 0 && kbetter(kv, c, rk[p - 1], ri[p - 1])) {
                rk[p] = rk[p - 1]; ri[p] = ri[p - 1]; p--;
            }
            rk[p] = kv; ri[p] = c;
        }
        __threadfence_block();
        atomicExch(lock, 0);
    }
}

__device__ __forceinline__ void mma16816(float* d, const unsigned* a,
                                         unsigned b0, unsigned b1) {
    asm volatile(
        "mma.sync.aligned.m16n8k16.row.col.f32.bf16.bf16.f32 "
        "{%0,%1,%2,%3},{%4,%5,%6,%7},{%8,%9},{%0,%1,%2,%3};"
        : "+f"(d[0]), "+f"(d[1]), "+f"(d[2]), "+f"(d[3])
        : "r"(a[0]), "r"(a[1]), "r"(a[2]), "r"(a[3]), "r"(b0), "r"(b1));
}

// ---------------------------------------------------------------------------
// Kernel 5: bf16 tensor-core approx-dist GEMM + per-row top-16 candidates
// key_approx = en[c] - 2*dot_bf16   (exact rescoring follows)
// ---------------------------------------------------------------------------
__global__ __launch_bounds__(256)
void k_mma() {
    __shared__ __align__(16) __nv_bfloat16 As[BM][APAD];
    __shared__ __align__(16) __nv_bfloat16 Bs[BN][APAD];
    __shared__ float s_key[BM][KCAND];
    __shared__ int   s_idx[BM][KCAND];
    __shared__ int   s_lock[BM];
    __shared__ float s_en[BN];

    const int tid  = threadIdx.x;
    const int wid  = tid >> 5;
    const int lane = tid & 31;
    const int g    = lane >> 2;     // groupID
    const int tig  = lane & 3;      // thread-in-group
    const int wm   = wid >> 1;      // warp row 0..3 (32 rows each)
    const int wn   = wid & 1;       // warp col 0..1 (64 cols each)
    const int row0 = blockIdx.x * BM;

    for (int r = tid; r < BM; r += 256) {
#pragma unroll
        for (int k = 0; k < KCAND; k++) { s_key[r][k] = FLT_MAX; s_idx[r][k] = 0x7fffffff; }
        s_lock[r] = 0;
    }
    __syncthreads();

    volatile float (*vkey)[KCAND] = (volatile float (*)[KCAND])s_key;
    volatile int   (*vidx)[KCAND] = (volatile int   (*)[KCAND])s_idx;

    for (int ct = 0; ct < NEMB / BN; ct++) {
        __syncthreads();                          // prev epilogue done before s_en overwrite
        if (tid < BN) s_en[tid] = g_enorm[ct * BN + tid];

        float d[2][8][4];
#pragma unroll
        for (int mt = 0; mt < 2; mt++)
#pragma unroll
            for (int nt = 0; nt < 8; nt++)
#pragma unroll
                for (int q = 0; q < 4; q++) d[mt][nt][q] = 0.f;

        for (int kt = 0; kt < DIM / KC; kt++) {
            __syncthreads();
            // load A and B chunks (128 x 32 bf16 each) as uint4
#pragma unroll
            for (int i = 0; i < 2; i++) {
                int idx = tid + i * 256;          // 0..511
                int r = idx >> 2, j = idx & 3;
                *(uint4*)&As[r][j * 8] =
                    *(const uint4*)&g_xbf[(size_t)(row0 + r) * DIM + kt * KC + j * 8];
                *(uint4*)&Bs[r][j * 8] =
                    *(const uint4*)&g_ebf[(size_t)(ct * BN + r) * DIM + kt * KC + j * 8];
            }
            __syncthreads();
#pragma unroll
            for (int kk = 0; kk < 2; kk++) {      // two k16 steps per chunk
                unsigned a[2][4];
#pragma unroll
                for (int mt = 0; mt < 2; mt++) {
                    int rb = wm * 32 + mt * 16;
                    a[mt][0] = *(const unsigned*)&As[rb + g][kk * 16 + tig * 2];
                    a[mt][1] = *(const unsigned*)&As[rb + g + 8][kk * 16 + tig * 2];
                    a[mt][2] = *(const unsigned*)&As[rb + g][kk * 16 + 8 + tig * 2];
                    a[mt][3] = *(const unsigned*)&As[rb + g + 8][kk * 16 + 8 + tig * 2];
                }
#pragma unroll
                for (int nt = 0; nt < 8; nt++) {
                    int cb = wn * 64 + nt * 8;
                    unsigned b0 = *(const unsigned*)&Bs[cb + g][kk * 16 + tig * 2];
                    unsigned b1 = *(const unsigned*)&Bs[cb + g][kk * 16 + 8 + tig * 2];
                    mma16816(d[0][nt], a[0], b0, b1);
                    mma16816(d[1][nt], a[1], b0, b1);
                }
            }
        }

        // Epilogue: approx keys in place, then rare-path inserts
#pragma unroll
        for (int mt = 0; mt < 2; mt++) {
            int r0 = wm * 32 + mt * 16 + g;
            int r1 = r0 + 8;
            float m0 = FLT_MAX, m1 = FLT_MAX;
#pragma unroll
            for (int nt = 0; nt < 8; nt++) {
                int col = wn * 64 + nt * 8 + tig * 2;
                d[mt][nt][0] = s_en[col]     - 2.f * d[mt][nt][0];
                d[mt][nt][1] = s_en[col + 1] - 2.f * d[mt][nt][1];
                d[mt][nt][2] = s_en[col]     - 2.f * d[mt][nt][2];
                d[mt][nt][3] = s_en[col + 1] - 2.f * d[mt][nt][3];
                m0 = fminf(m0, fminf(d[mt][nt][0], d[mt][nt][1]));
                m1 = fminf(m1, fminf(d[mt][nt][2], d[mt][nt][3]));
            }
            if (m0 <= vkey[r0][KCAND - 1]) {
                for (int nt = 0; nt < 8; nt++) {
                    int col = ct * BN + wn * 64 + nt * 8 + tig * 2;
                    try_insert(vkey[r0], vidx[r0], &s_lock[r0], d[mt][nt][0], col);
                    try_insert(vkey[r0], vidx[r0], &s_lock[r0], d[mt][nt][1], col + 1);
                }
            }
            if (m1 <= vkey[r1][KCAND - 1]) {
                for (int nt = 0; nt < 8; nt++) {
                    int col = ct * BN + wn * 64 + nt * 8 + tig * 2;
                    try_insert(vkey[r1], vidx[r1], &s_lock[r1], d[mt][nt][2], col);
                    try_insert(vkey[r1], vidx[r1], &s_lock[r1], d[mt][nt][3], col + 1);
                }
            }
        }
    }
    __syncthreads();

    for (int e = tid; e < BM * KCAND; e += 256) {
        int r = e / KCAND, k = e % KCAND;
        g_cand[(size_t)(row0 + r) * KCAND + k] = s_idx[r][k];
    }
}

// ---------------------------------------------------------------------------
// Kernel 6: exact rescoring of 16 candidates/row — reproduces the validated
// R11 numerics: ascending-k scalar fma chain, same en/xn, same epilogue,
// hi-index tie order; exports top-4 + top-2 keys.
// ---------------------------------------------------------------------------
__global__ __launch_bounds__(256)
void k_refine(const float* __restrict__ input) {
    const int lrow = threadIdx.x >> 4;          // 0..15
    const int slot = threadIdx.x & 15;          // 0..15
    const int row  = blockIdx.x * 16 + lrow;
    const int c    = g_cand[(size_t)row * KCAND + slot];
    const float* x = input   + (size_t)row * DIM;
    const float* e = g_codeT + (size_t)c   * DIM;
    float s = 0.f;
#pragma unroll 8
    for (int k = 0; k < DIM; k++) s = __fmaf_rn(x[k], e[k], s);
    float key = __fadd_rn(__fsub_rn(g_xnorm[row], __fmul_rn(2.0f, s)), g_enorm[c]);

    __shared__ float sk[16][16];
    __shared__ int   si[16][16];
    sk[lrow][slot] = key;
    si[lrow][slot] = c;
    __syncthreads();

    if (slot == 0) {
        float k[KCAND]; int id[KCAND];
#pragma unroll
        for (int i = 0; i < KCAND; i++) { k[i] = sk[lrow][i]; id[i] = si[lrow][i]; }
#pragma unroll
        for (int i = 1; i < KCAND; i++) {
            float kv = k[i]; int iv = id[i];
            int p = i;
            while (p > 0 && kbetter(kv, iv, k[p - 1], id[p - 1])) {
                k[p] = k[p - 1]; id[p] = id[p - 1]; p--;
            }
            k[p] = kv; id[p] = iv;
        }
#pragma unroll
        for (int i = 0; i < KTOP; i++) g_top[(size_t)row * KTOP + i] = id[i];
        g_key2[(size_t)row * 2 + 0] = k[0];
        g_key2[(size_t)row * 2 + 1] = k[1];
    }
}

// ---------------------------------------------------------------------------
// Kernel 7: outputs — topk gather as float4 (out_topk is 16B-aligned);
// out_st stream uses SCALAR stores (pointer is offset by +1 float -> only
// 4-byte aligned). ST + diff use argmax low-index tie policy via top-2 keys.
// ---------------------------------------------------------------------------
__global__ __launch_bounds__(256)
void k_out(const float* __restrict__ input,
           float* __restrict__ out_topk, float* __restrict__ out_st) {
    const int tid = threadIdx.x;
    const int gsz = gridDim.x * blockDim.x;
    const int gid = blockIdx.x * blockDim.x + tid;
    const float4* codeT4 = (const float4*)g_codeT;

    for (int e = gid; e < N_ROWS * KTOP * DIM / 4; e += gsz) {
        int r  = e >> 8;
        int k  = (e >> 6) & 3;
        int d4 = e & 63;
        int c  = g_top[(size_t)r * KTOP + k];
        ((float4*)out_topk)[e] = codeT4[(size_t)c * 64 + d4];
    }
    double part = 0.0;
    for (int e = gid; e < N_ROWS * DIM / 4; e += gsz) {
        int r  = e >> 6;
        int d4 = e & 63;
        int i0 = g_top[(size_t)r * KTOP + 0];
        int i1 = g_top[(size_t)r * KTOP + 1];
        float k0 = g_key2[(size_t)r * 2 + 0];
        float k1 = g_key2[(size_t)r * 2 + 1];
        int c = (k0 == k1) ? min(i0, i1) : i0;    // argmax: low-index tie-break
        float4 q = codeT4[(size_t)c * 64 + d4];
        float4 x = ((const float4*)input)[e];     // input is 16B-aligned
        // out_st is only 4B-aligned (+1 float offset) -> scalar stores
        out_st[e * 4 + 0] = __fadd_rn(x.x, __fsub_rn(q.x, x.x));
        out_st[e * 4 + 1] = __fadd_rn(x.y, __fsub_rn(q.y, x.y));
        out_st[e * 4 + 2] = __fadd_rn(x.z, __fsub_rn(q.z, x.z));
        out_st[e * 4 + 3] = __fadd_rn(x.w, __fsub_rn(q.w, x.w));
        double dx = (double)q.x - (double)x.x, dy = (double)q.y - (double)x.y;
        double dz = (double)q.z - (double)x.z, dw = (double)q.w - (double)x.w;
        part += dx * dx + dy * dy + dz * dz + dw * dw;
    }
#pragma unroll
    for (int o = 16; o; o >>= 1) part += __shfl_xor_sync(0xffffffffu, part, o);
    __shared__ double s_red[8];
    if ((tid & 31) == 0) s_red[tid >> 5] = part;
    __syncthreads();
    if (tid == 0) {
        double t = 0.0;
#pragma unroll
        for (int i = 0; i < 8; i++) t += s_red[i];
        g_partial[blockIdx.x] = t;
    }
}

// ---------------------------------------------------------------------------
// Kernel 8: deterministic diff reduction
// ---------------------------------------------------------------------------
__global__ void k_diff(float* __restrict__ out_diff) {
    if (threadIdx.x == 0) {
        double s = 0.0;
        for (int i = 0; i < OUTBLOCKS; i++) s += g_partial[i];
        out_diff[0] = (float)(s / (double)((long)N_ROWS * DIM));
    }
}

// ---------------------------------------------------------------------------
extern "C" void kernel_launch(void* const* d_in, const int* in_sizes, int n_in,
                              void* d_out, int out_size) {
    const float* input = (const float*)d_in[0];
    const float* embed = (const float*)d_in[1];
    if (n_in >= 2 && in_sizes[0] == NEMB * DIM && in_sizes[1] == N_ROWS * DIM) {
        input = (const float*)d_in[1];
        embed = (const float*)d_in[0];
    }
    float* out      = (float*)d_out;
    float* out_topk = out;                                  // 16384*1024
    float* out_diff = out + (size_t)N_ROWS * KTOP * DIM;    // 1
    float* out_st   = out_diff + 1;                         // 16384*256

    k_transpose<<<dim3(NEMB / 32, DIM / 32), dim3(32, 8)>>>(embed);
    k_enorm<<<NEMB / 32, dim3(32, 32)>>>(embed);
    k_xnorm<<<N_ROWS / 8, 256>>>(input);
    k_xbf<<<1024, 256>>>(input);
    k_mma<<<N_ROWS / BM, 256>>>();
    k_refine<<<N_ROWS / 16, 256>>>(input);
    k_out<<<OUTBLOCKS, 256>>>(input, out_topk, out_st);
    k_diff<<<1, 32>>>(out_diff);
}

// round 14
// speedup vs baseline: 2.7130x; 2.7130x over previous
#include <cuda_runtime.h>
#include <cuda_bf16.h>
#include <cstdint>
#include <float.h>

// Problem constants
#define N_ROWS 16384   // 16*32*32
#define DIM    256
#define NEMB   2048
#define KTOP   4
#define KCAND  16      // merged candidates per row (exact-rescored)
#define KPRIV  8       // private per-thread top-K per row

#define BM 128
#define BN 128
#define KC 32          // k-chunk in the mma kernel
#define APAD 40        // padded smem row (bf16): conflict-free frags, 16B aligned
#define OUTBLOCKS 512

// Scratch (no cudaMalloc allowed)
__device__ float g_codeT[NEMB * DIM];                       // codebook [code][dim] fp32
__device__ __align__(16) __nv_bfloat16 g_ebf[NEMB * DIM];   // bf16 codebook [code][dim]
__device__ __align__(16) __nv_bfloat16 g_xbf[N_ROWS * DIM]; // bf16 input rows
__device__ float g_enorm[NEMB];          // ||e||^2 (R11 exact emitter)
__device__ float g_xnorm[N_ROWS];        // ||x||^2 (R11 form)
__device__ int   g_cand[N_ROWS * KCAND]; // approx top-16 indices
__device__ int   g_top[N_ROWS * KTOP];   // exact top-4 (hi-index tie policy)
__device__ float g_key2[N_ROWS * 2];     // exact top-2 keys (argmax low-index policy)
__device__ double g_partial[OUTBLOCKS];

// ---------------------------------------------------------------------------
// Kernel 1: transpose embed [DIM][NEMB] -> codeT [NEMB][DIM] (+ bf16 copy)
// ---------------------------------------------------------------------------
__global__ void k_transpose(const float* __restrict__ embed) {
    __shared__ float t[32][33];
    int c = blockIdx.x * 32 + threadIdx.x;
#pragma unroll
    for (int j = 0; j < 4; j++) {
        int d = blockIdx.y * 32 + threadIdx.y + j * 8;
        t[threadIdx.y + j * 8][threadIdx.x] = embed[d * NEMB + c];
    }
    __syncthreads();
    int d = blockIdx.y * 32 + threadIdx.x;
#pragma unroll
    for (int j = 0; j < 4; j++) {
        int c2 = blockIdx.x * 32 + threadIdx.y + j * 8;
        float v = t[threadIdx.x][threadIdx.y + j * 8];
        g_codeT[c2 * DIM + d] = v;
        g_ebf[c2 * DIM + d]   = __float2bfloat16(v);
    }
}

// ---------------------------------------------------------------------------
// Kernel 2: ||e_c||^2 — EXACT R11 emitter (fma partials stride-32, tree32)
// ---------------------------------------------------------------------------
__global__ void k_enorm(const float* __restrict__ embed) {
    __shared__ float p[32][33];
    int c  = blockIdx.x * 32 + threadIdx.x;
    int ty = threadIdx.y;
    float s = 0.f;
#pragma unroll
    for (int i = 0; i < DIM / 32; i++) {
        float v = embed[(size_t)(ty + 32 * i) * NEMB + c];
        s = __fmaf_rn(v, v, s);
    }
    p[ty][threadIdx.x] = s;
    __syncthreads();
#pragma unroll
    for (int step = 16; step > 0; step >>= 1) {
        if (ty < step) p[ty][threadIdx.x] = __fadd_rn(p[ty][threadIdx.x], p[ty + step][threadIdx.x]);
        __syncthreads();
    }
    if (ty == 0) g_enorm[c] = p[0][threadIdx.x];
}

// ---------------------------------------------------------------------------
// Kernel 3: ||x_r||^2 (R11 form)
// ---------------------------------------------------------------------------
__global__ void k_xnorm(const float* __restrict__ input) {
    int row  = blockIdx.x * 8 + (threadIdx.x >> 5);
    int lane = threadIdx.x & 31;
    float s = 0.f;
#pragma unroll
    for (int i = 0; i < DIM / 32; i++) {
        float v = input[(size_t)row * DIM + lane + 32 * i];
        s = __fmaf_rn(v, v, s);
    }
#pragma unroll
    for (int o = 16; o; o >>= 1)
        s = __fadd_rn(s, __shfl_down_sync(0xffffffffu, s, o));
    if (lane == 0) g_xnorm[row] = s;
}

// ---------------------------------------------------------------------------
// Kernel 4: input -> bf16
// ---------------------------------------------------------------------------
__global__ void k_xbf(const float* __restrict__ input) {
    int gsz = gridDim.x * blockDim.x;
    for (int i = blockIdx.x * blockDim.x + threadIdx.x; i < N_ROWS * DIM / 2; i += gsz) {
        float2 v = ((const float2*)input)[i];
        __nv_bfloat162 h;
        h.x = __float2bfloat16(v.x);
        h.y = __float2bfloat16(v.y);
        ((__nv_bfloat162*)g_xbf)[i] = h;
    }
}

// Tie order (XLA TopK bitonic): smaller key wins; exact tie -> HIGHER index.
__device__ __forceinline__ bool kbetter(float k1, int i1, float k2, int i2) {
    return (k1 < k2) || (k1 == k2 && i1 > i2);
}

// Bubble a candidate into a sorted (best-first) private register list of 8.
__device__ __forceinline__ void ins8(float* lk, int* li, float kv, int c) {
    if (!kbetter(kv, c, lk[KPRIV - 1], li[KPRIV - 1])) return;
    float ck = kv; int ci = c;
#pragma unroll
    for (int p = 0; p < KPRIV; p++) {
        if (kbetter(ck, ci, lk[p], li[p])) {
            float tk = lk[p]; int ti = li[p];
            lk[p] = ck; li[p] = ci;
            ck = tk; ci = ti;
        }
    }
}

__device__ __forceinline__ void mma16816(float* d, const unsigned* a,
                                         unsigned b0, unsigned b1) {
    asm volatile(
        "mma.sync.aligned.m16n8k16.row.col.f32.bf16.bf16.f32 "
        "{%0,%1,%2,%3},{%4,%5,%6,%7},{%8,%9},{%0,%1,%2,%3};"
        : "+f"(d[0]), "+f"(d[1]), "+f"(d[2]), "+f"(d[3])
        : "r"(a[0]), "r"(a[1]), "r"(a[2]), "r"(a[3]), "r"(b0), "r"(b1));
}

// ---------------------------------------------------------------------------
// Kernel 5: bf16 tensor-core approx-dist GEMM, lock-free top-16 candidates.
// Warp w owns rows [16w,16w+16) x all 128 cols; each thread keeps private
// register top-8 per owned row; single-owner 4-phase merge at the end.
// key_approx = en[c] - 2*dot_bf16   (exact rescoring follows)
// ---------------------------------------------------------------------------
__global__ __launch_bounds__(256)
void k_mma() {
    __shared__ __align__(16) __nv_bfloat16 As[BM][APAD];
    __shared__ __align__(16) __nv_bfloat16 Bs[BN][APAD];
    __shared__ float s_key[BM][KCAND];
    __shared__ int   s_idx[BM][KCAND];
    __shared__ float s_en[BN];

    const int tid  = threadIdx.x;
    const int wid  = tid >> 5;      // warp 0..7 -> rows [16w, 16w+16)
    const int lane = tid & 31;
    const int g    = lane >> 2;     // groupID 0..7
    const int tig  = lane & 3;      // thread-in-group 0..3
    const int rb   = wid * 16;
    const int row0 = blockIdx.x * BM;

    // private top-8 lists for the two owned rows (rb+g and rb+g+8)
    float lk0[KPRIV], lk1[KPRIV];
    int   li0[KPRIV], li1[KPRIV];
#pragma unroll
    for (int p = 0; p < KPRIV; p++) {
        lk0[p] = FLT_MAX; lk1[p] = FLT_MAX;
        li0[p] = 0x7fffffff; li1[p] = 0x7fffffff;
    }

    for (int ct = 0; ct < NEMB / BN; ct++) {
        __syncthreads();
        if (tid < BN) s_en[tid] = g_enorm[ct * BN + tid];

        float d[16][4];
#pragma unroll
        for (int nt = 0; nt < 16; nt++)
#pragma unroll
            for (int q = 0; q < 4; q++) d[nt][q] = 0.f;

        for (int kt = 0; kt < DIM / KC; kt++) {
            __syncthreads();
            // load A and B chunks (128 x 32 bf16 each) as uint4
#pragma unroll
            for (int i = 0; i < 2; i++) {
                int idx = tid + i * 256;          // 0..511
                int r = idx >> 2, j = idx & 3;
                *(uint4*)&As[r][j * 8] =
                    *(const uint4*)&g_xbf[(size_t)(row0 + r) * DIM + kt * KC + j * 8];
                *(uint4*)&Bs[r][j * 8] =
                    *(const uint4*)&g_ebf[(size_t)(ct * BN + r) * DIM + kt * KC + j * 8];
            }
            __syncthreads();
#pragma unroll
            for (int kk = 0; kk < 2; kk++) {      // two k16 steps per chunk
                unsigned a[4];
                a[0] = *(const unsigned*)&As[rb + g][kk * 16 + tig * 2];
                a[1] = *(const unsigned*)&As[rb + g + 8][kk * 16 + tig * 2];
                a[2] = *(const unsigned*)&As[rb + g][kk * 16 + 8 + tig * 2];
                a[3] = *(const unsigned*)&As[rb + g + 8][kk * 16 + 8 + tig * 2];
#pragma unroll
                for (int nt = 0; nt < 16; nt++) {
                    unsigned b0 = *(const unsigned*)&Bs[nt * 8 + g][kk * 16 + tig * 2];
                    unsigned b1 = *(const unsigned*)&Bs[nt * 8 + g][kk * 16 + 8 + tig * 2];
                    mma16816(d[nt], a, b0, b1);
                }
            }
        }

        // Epilogue: approx keys -> private register lists (no atomics)
#pragma unroll
        for (int nt = 0; nt < 16; nt++) {
            int cloc = nt * 8 + tig * 2;
            int c0   = ct * BN + cloc;
            float e0 = s_en[cloc], e1 = s_en[cloc + 1];
            ins8(lk0, li0, e0 - 2.f * d[nt][0], c0);
            ins8(lk0, li0, e1 - 2.f * d[nt][1], c0 + 1);
            ins8(lk1, li1, e0 - 2.f * d[nt][2], c0);
            ins8(lk1, li1, e1 - 2.f * d[nt][3], c0 + 1);
        }
    }

    // ---- Merge: init smem lists, then 4 single-owner phases per row ----
    __syncthreads();
    for (int r = tid; r < BM; r += 256) {
#pragma unroll
        for (int k = 0; k < KCAND; k++) { s_key[r][k] = FLT_MAX; s_idx[r][k] = 0x7fffffff; }
    }
    __syncthreads();
#pragma unroll
    for (int ph = 0; ph < 4; ph++) {
        if (tig == ph) {
#pragma unroll
            for (int which = 0; which < 2; which++) {
                int r = rb + g + which * 8;
                float* lk = which ? lk1 : lk0;
                int*   li = which ? li1 : li0;
                for (int i = 0; i < KPRIV; i++) {
                    float kv = lk[i]; int c = li[i];
                    if (!kbetter(kv, c, s_key[r][KCAND - 1], s_idx[r][KCAND - 1])) break;
                    int p = KCAND - 1;
                    while (p > 0 && kbetter(kv, c, s_key[r][p - 1], s_idx[r][p - 1])) {
                        s_key[r][p] = s_key[r][p - 1];
                        s_idx[r][p] = s_idx[r][p - 1];
                        p--;
                    }
                    s_key[r][p] = kv; s_idx[r][p] = c;
                }
            }
        }
        __syncthreads();
    }

    for (int e = tid; e < BM * KCAND; e += 256) {
        int r = e / KCAND, k = e % KCAND;
        g_cand[(size_t)(row0 + r) * KCAND + k] = s_idx[r][k];
    }
}

// ---------------------------------------------------------------------------
// Kernel 6: exact rescoring of 16 candidates/row — bit-identical R11 numerics:
// ascending-k scalar fma chain (float4 loads, scalar-order fma), same en/xn,
// same epilogue, hi-index tie order; exports top-4 + top-2 keys.
// ---------------------------------------------------------------------------
__global__ __launch_bounds__(256)
void k_refine(const float* __restrict__ input) {
    const int lrow = threadIdx.x >> 4;          // 0..15
    const int slot = threadIdx.x & 15;          // 0..15
    const int row  = blockIdx.x * 16 + lrow;
    const int c    = g_cand[(size_t)row * KCAND + slot];
    const float4* x4 = (const float4*)(input   + (size_t)row * DIM);
    const float4* e4 = (const float4*)(g_codeT + (size_t)c   * DIM);
    float s = 0.f;
#pragma unroll 8
    for (int k4 = 0; k4 < DIM / 4; k4++) {
        float4 a = x4[k4];
        float4 b = e4[k4];
        s = __fmaf_rn(a.x, b.x, s);             // k ascending: bit-identical chain
        s = __fmaf_rn(a.y, b.y, s);
        s = __fmaf_rn(a.z, b.z, s);
        s = __fmaf_rn(a.w, b.w, s);
    }
    float key = __fadd_rn(__fsub_rn(g_xnorm[row], __fmul_rn(2.0f, s)), g_enorm[c]);

    __shared__ float sk[16][16];
    __shared__ int   si[16][16];
    sk[lrow][slot] = key;
    si[lrow][slot] = c;
    __syncthreads();

    if (slot == 0) {
        float k[KCAND]; int id[KCAND];
#pragma unroll
        for (int i = 0; i < KCAND; i++) { k[i] = sk[lrow][i]; id[i] = si[lrow][i]; }
#pragma unroll
        for (int i = 1; i < KCAND; i++) {
            float kv = k[i]; int iv = id[i];
            int p = i;
            while (p > 0 && kbetter(kv, iv, k[p - 1], id[p - 1])) {
                k[p] = k[p - 1]; id[p] = id[p - 1]; p--;
            }
            k[p] = kv; id[p] = iv;
        }
#pragma unroll
        for (int i = 0; i < KTOP; i++) g_top[(size_t)row * KTOP + i] = id[i];
        g_key2[(size_t)row * 2 + 0] = k[0];
        g_key2[(size_t)row * 2 + 1] = k[1];
    }
}

// ---------------------------------------------------------------------------
// Kernel 7: outputs — topk gather as float4 (out_topk 16B-aligned);
// out_st written with scalar stores (pointer offset +1 float -> 4B-aligned).
// ST + diff use argmax low-index tie policy via top-2 keys.
// ---------------------------------------------------------------------------
__global__ __launch_bounds__(256)
void k_out(const float* __restrict__ input,
           float* __restrict__ out_topk, float* __restrict__ out_st) {
    const int tid = threadIdx.x;
    const int gsz = gridDim.x * blockDim.x;
    const int gid = blockIdx.x * blockDim.x + tid;
    const float4* codeT4 = (const float4*)g_codeT;

    for (int e = gid; e < N_ROWS * KTOP * DIM / 4; e += gsz) {
        int r  = e >> 8;
        int k  = (e >> 6) & 3;
        int d4 = e & 63;
        int c  = g_top[(size_t)r * KTOP + k];
        ((float4*)out_topk)[e] = codeT4[(size_t)c * 64 + d4];
    }
    double part = 0.0;
    for (int e = gid; e < N_ROWS * DIM / 4; e += gsz) {
        int r  = e >> 6;
        int d4 = e & 63;
        int i0 = g_top[(size_t)r * KTOP + 0];
        int i1 = g_top[(size_t)r * KTOP + 1];
        float k0 = g_key2[(size_t)r * 2 + 0];
        float k1 = g_key2[(size_t)r * 2 + 1];
        int c = (k0 == k1) ? min(i0, i1) : i0;    // argmax: low-index tie-break
        float4 q = codeT4[(size_t)c * 64 + d4];
        float4 x = ((const float4*)input)[e];
        out_st[e * 4 + 0] = __fadd_rn(x.x, __fsub_rn(q.x, x.x));
        out_st[e * 4 + 1] = __fadd_rn(x.y, __fsub_rn(q.y, x.y));
        out_st[e * 4 + 2] = __fadd_rn(x.z, __fsub_rn(q.z, x.z));
        out_st[e * 4 + 3] = __fadd_rn(x.w, __fsub_rn(q.w, x.w));
        double dx = (double)q.x - (double)x.x, dy = (double)q.y - (double)x.y;
        double dz = (double)q.z - (double)x.z, dw = (double)q.w - (double)x.w;
        part += dx * dx + dy * dy + dz * dz + dw * dw;
    }
#pragma unroll
    for (int o = 16; o; o >>= 1) part += __shfl_xor_sync(0xffffffffu, part, o);
    __shared__ double s_red[8];
    if ((tid & 31) == 0) s_red[tid >> 5] = part;
    __syncthreads();
    if (tid == 0) {
        double t = 0.0;
#pragma unroll
        for (int i = 0; i < 8; i++) t += s_red[i];
        g_partial[blockIdx.x] = t;
    }
}

// ---------------------------------------------------------------------------
// Kernel 8: deterministic diff reduction
// ---------------------------------------------------------------------------
__global__ void k_diff(float* __restrict__ out_diff) {
    if (threadIdx.x == 0) {
        double s = 0.0;
        for (int i = 0; i < OUTBLOCKS; i++) s += g_partial[i];
        out_diff[0] = (float)(s / (double)((long)N_ROWS * DIM));
    }
}

// ---------------------------------------------------------------------------
extern "C" void kernel_launch(void* const* d_in, const int* in_sizes, int n_in,
                              void* d_out, int out_size) {
    const float* input = (const float*)d_in[0];
    const float* embed = (const float*)d_in[1];
    if (n_in >= 2 && in_sizes[0] == NEMB * DIM && in_sizes[1] == N_ROWS * DIM) {
        input = (const float*)d_in[1];
        embed = (const float*)d_in[0];
    }
    float* out      = (float*)d_out;
    float* out_topk = out;                                  // 16384*1024
    float* out_diff = out + (size_t)N_ROWS * KTOP * DIM;    // 1
    float* out_st   = out_diff + 1;                         // 16384*256

    k_transpose<<<dim3(NEMB / 32, DIM / 32), dim3(32, 8)>>>(embed);
    k_enorm<<<NEMB / 32, dim3(32, 32)>>>(embed);
    k_xnorm<<<N_ROWS / 8, 256>>>(input);
    k_xbf<<<1024, 256>>>(input);
    k_mma<<<N_ROWS / BM, 256>>>();
    k_refine<<<N_ROWS / 16, 256>>>(input);
    k_out<<<OUTBLOCKS, 256>>>(input, out_topk, out_st);
    k_diff<<<1, 32>>>(out_diff);
}